// round 1
// baseline (speedup 1.0000x reference)
#include <cuda_runtime.h>

#define NN   10000
#define EE   160000
#define FIN  1152
#define FOUT 288
#define KMAX 7
#define LDT  (KMAX*FIN)   /* 8064 */
#define LDT4 (LDT/4)      /* 2016 */

// ---------------- device scratch (static globals; no runtime alloc) ----------
__device__ float4 g_T4[(size_t)KMAX * NN * (FIN/4)];   // ~322.6 MB, T[node][k][f]
#define G_T ((float*)g_T4)

__device__ int   g_deg[NN];
__device__ float g_dinv[NN];
__device__ int   g_cnt[NN];
__device__ int   g_colptr[NN + 1];
__device__ int   g_cursor[NN];
__device__ int   g_src[EE];
__device__ float g_w[EE];

// ---------------- setup kernels ----------------------------------------------
__global__ void k_zero() {
    int i = blockIdx.x * blockDim.x + threadIdx.x;
    if (i < NN) { g_deg[i] = 0; g_cnt[i] = 0; g_cursor[i] = 0; }
}

__global__ void k_hist(const int* __restrict__ ei) {
    int e = blockIdx.x * blockDim.x + threadIdx.x;
    if (e < EE) {
        atomicAdd(&g_deg[ei[e]], 1);        // out-degree by row (source)
        atomicAdd(&g_cnt[ei[EE + e]], 1);   // in-degree histogram by col (target)
    }
}

__global__ void k_dinv() {
    int i = blockIdx.x * blockDim.x + threadIdx.x;
    if (i < NN) {
        int d = g_deg[i];
        g_dinv[i] = (d > 0) ? rsqrtf((float)d) : 0.0f;
    }
}

// single-block exclusive scan of g_cnt -> g_colptr
__global__ void k_scan() {
    __shared__ int sh[1024];
    __shared__ int s_carry;
    const int tid = threadIdx.x;
    if (tid == 0) s_carry = 0;
    __syncthreads();
    for (int base = 0; base < NN; base += 1024) {
        int i = base + tid;
        int v = (i < NN) ? g_cnt[i] : 0;
        sh[tid] = v;
        __syncthreads();
        for (int off = 1; off < 1024; off <<= 1) {
            int tv = (tid >= off) ? sh[tid - off] : 0;
            __syncthreads();
            sh[tid] += tv;
            __syncthreads();
        }
        int carry = s_carry;
        if (i < NN) g_colptr[i] = carry + sh[tid] - v;
        __syncthreads();
        if (tid == 0) s_carry = carry + sh[1023];
        __syncthreads();
    }
    if (tid == 0) g_colptr[NN] = s_carry;
}

__global__ void k_scatter(const int* __restrict__ ei) {
    int e = blockIdx.x * blockDim.x + threadIdx.x;
    if (e < EE) {
        int r = ei[e];
        int c = ei[EE + e];
        int p = g_colptr[c] + atomicAdd(&g_cursor[c], 1);
        g_src[p] = r;
        g_w[p]   = -(g_dinv[r] * g_dinv[c]);
    }
}

__global__ void k_copyx(const float* __restrict__ x) {
    const int total = NN * (FIN / 4);
    for (int idx = blockIdx.x * blockDim.x + threadIdx.x; idx < total;
         idx += gridDim.x * blockDim.x) {
        int node = idx / (FIN / 4);
        int r    = idx - node * (FIN / 4);
        g_T4[(size_t)node * LDT4 + r] = ((const float4*)x)[idx];
    }
}

// ---------------- Chebyshev propagation --------------------------------------
// T_k[i,:] = 2 * sum_{e: col=i} w_e * T_{k-1}[src_e,:]  -  T_{k-2}[i,:]
// (k==1: T_1 = prop(T_0), no 2x / subtract)
__global__ void k_prop(int kcur) {
    const int node = blockIdx.x;
    const int tid  = threadIdx.x;            // 288 threads, each owns a float4
    const int beg  = g_colptr[node];
    const int end  = g_colptr[node + 1];

    __shared__ int   ss[64];
    __shared__ float sw[64];

    float4 acc = make_float4(0.f, 0.f, 0.f, 0.f);
    const size_t foff  = (size_t)tid * 4;
    const size_t kprev = (size_t)(kcur - 1) * FIN;

    for (int b0 = beg; b0 < end; b0 += 64) {
        int cnt = min(64, end - b0);
        __syncthreads();
        if (tid < cnt) { ss[tid] = g_src[b0 + tid]; sw[tid] = g_w[b0 + tid]; }
        __syncthreads();
        for (int j = 0; j < cnt; j++) {
            float w = sw[j];
            const float4 v = *(const float4*)(G_T + (size_t)ss[j] * LDT + kprev + foff);
            acc.x += w * v.x; acc.y += w * v.y; acc.z += w * v.z; acc.w += w * v.w;
        }
    }

    const size_t nb = (size_t)node * LDT;
    float4 r;
    if (kcur == 1) {
        r = acc;
    } else {
        const float4 p = *(const float4*)(G_T + nb + (size_t)(kcur - 2) * FIN + foff);
        r.x = 2.f * acc.x - p.x; r.y = 2.f * acc.y - p.y;
        r.z = 2.f * acc.z - p.z; r.w = 2.f * acc.w - p.w;
    }
    *(float4*)(G_T + nb + (size_t)kcur * FIN + foff) = r;
}

// ---------------- dense contraction (f32x2 SGEMM) -----------------------------
#define BM   128
#define BN   96
#define BKK  16
#define APAD 17

__device__ __forceinline__ unsigned long long ffma2(unsigned long long a,
                                                    unsigned long long b,
                                                    unsigned long long c) {
    unsigned long long d;
    asm("fma.rn.f32x2 %0, %1, %2, %3;" : "=l"(d) : "l"(a), "l"(b), "l"(c));
    return d;
}
__device__ __forceinline__ unsigned long long dup2(float v) {
    unsigned long long d;
    asm("mov.b64 %0, {%1, %1};" : "=l"(d) : "f"(v));
    return d;
}
__device__ __forceinline__ float2 unpk2(unsigned long long a) {
    float2 r;
    asm("mov.b64 {%0, %1}, %2;" : "=f"(r.x), "=f"(r.y) : "l"(a));
    return r;
}

// grid: (3, ceil(N/128), 4 convs), 256 threads
__global__ void __launch_bounds__(256, 2) k_gemm(
    const float* __restrict__ W0, const float* __restrict__ W1,
    const float* __restrict__ W2, const float* __restrict__ W3,
    const float* __restrict__ B0, const float* __restrict__ B1,
    const float* __restrict__ B2, const float* __restrict__ B3,
    float* __restrict__ out)
{
    __shared__ __align__(16) float As[2][BM][APAD];
    __shared__ __align__(16) float Bs[2][BKK][BN];

    const int c  = blockIdx.z;
    const int Kc = 4 + c;                       // KS = {4,5,6,7}
    const float* W  = (c == 0) ? W0 : (c == 1) ? W1 : (c == 2) ? W2 : W3;
    const float* Bv = (c == 0) ? B0 : (c == 1) ? B1 : (c == 2) ? B2 : B3;
    const int KT = Kc * FIN;
    const int m0 = blockIdx.y * BM;
    const int n0 = blockIdx.x * BN;
    const int t  = threadIdx.x;
    const int tx = t & 15;
    const int ty = t >> 4;

    // A staging: 2 x float4 per thread per tile
    const int aidx0 = t, aidx1 = t + 256;
    const int arow0 = aidx0 >> 2, ac0 = (aidx0 & 3) * 4;
    const int arow1 = aidx1 >> 2, ac1 = (aidx1 & 3) * 4;
    const int gm0 = min(m0 + arow0, NN - 1);
    const int gm1 = min(m0 + arow1, NN - 1);
    const float* a_base0 = G_T + (size_t)gm0 * LDT + ac0;
    const float* a_base1 = G_T + (size_t)gm1 * LDT + ac1;

    // B staging: 3 x float2 per thread per tile
    int brow[3], bcol[3];
#pragma unroll
    for (int j = 0; j < 3; j++) {
        int f2 = t + 256 * j;
        brow[j] = f2 / 48;
        bcol[j] = (f2 % 48) * 2;
    }

    unsigned long long acc[8][3];
#pragma unroll
    for (int i = 0; i < 8; i++)
#pragma unroll
        for (int j = 0; j < 3; j++) acc[i][j] = 0ull;

    float4 areg0, areg1;
    float2 breg[3];

    // prologue: tile 0 -> smem buf 0
    areg0 = *(const float4*)(a_base0);
    areg1 = *(const float4*)(a_base1);
#pragma unroll
    for (int j = 0; j < 3; j++)
        breg[j] = *(const float2*)&W[(size_t)brow[j] * FOUT + n0 + bcol[j]];

    As[0][arow0][ac0 + 0] = areg0.x; As[0][arow0][ac0 + 1] = areg0.y;
    As[0][arow0][ac0 + 2] = areg0.z; As[0][arow0][ac0 + 3] = areg0.w;
    As[0][arow1][ac1 + 0] = areg1.x; As[0][arow1][ac1 + 1] = areg1.y;
    As[0][arow1][ac1 + 2] = areg1.z; As[0][arow1][ac1 + 3] = areg1.w;
#pragma unroll
    for (int j = 0; j < 3; j++)
        *(float2*)&Bs[0][brow[j]][bcol[j]] = breg[j];
    __syncthreads();

    const int ntiles = KT / BKK;
    for (int tile = 0; tile < ntiles; ++tile) {
        const int  cur  = tile & 1;
        const bool more = (tile + 1 < ntiles);
        const int  k0n  = (tile + 1) * BKK;

        if (more) {
            areg0 = *(const float4*)(a_base0 + k0n);
            areg1 = *(const float4*)(a_base1 + k0n);
#pragma unroll
            for (int j = 0; j < 3; j++)
                breg[j] = *(const float2*)&W[(size_t)(k0n + brow[j]) * FOUT + n0 + bcol[j]];
        }

#pragma unroll
        for (int k = 0; k < BKK; k++) {
            float a[8];
#pragma unroll
            for (int i = 0; i < 8; i++) a[i] = As[cur][ty * 8 + i][k];
            unsigned long long b2[3];
#pragma unroll
            for (int j = 0; j < 3; j++)
                b2[j] = *reinterpret_cast<const unsigned long long*>(
                            &Bs[cur][k][tx * 6 + 2 * j]);
#pragma unroll
            for (int i = 0; i < 8; i++) {
                unsigned long long ad = dup2(a[i]);
#pragma unroll
                for (int j = 0; j < 3; j++)
                    acc[i][j] = ffma2(ad, b2[j], acc[i][j]);
            }
        }

        if (more) {
            const int nxt = cur ^ 1;
            As[nxt][arow0][ac0 + 0] = areg0.x; As[nxt][arow0][ac0 + 1] = areg0.y;
            As[nxt][arow0][ac0 + 2] = areg0.z; As[nxt][arow0][ac0 + 3] = areg0.w;
            As[nxt][arow1][ac1 + 0] = areg1.x; As[nxt][arow1][ac1 + 1] = areg1.y;
            As[nxt][arow1][ac1 + 2] = areg1.z; As[nxt][arow1][ac1 + 3] = areg1.w;
#pragma unroll
            for (int j = 0; j < 3; j++)
                *(float2*)&Bs[nxt][brow[j]][bcol[j]] = breg[j];
            __syncthreads();
        }
    }

    // epilogue
#pragma unroll
    for (int i = 0; i < 8; i++) {
        int gm = m0 + ty * 8 + i;
        if (gm < NN) {
            float* orow = out + (size_t)gm * 1152 + c * FOUT + n0 + tx * 6;
#pragma unroll
            for (int j = 0; j < 3; j++) {
                float2 v = unpk2(acc[i][j]);
                int cb = n0 + tx * 6 + 2 * j;
                orow[2 * j]     = v.x + Bv[cb];
                orow[2 * j + 1] = v.y + Bv[cb + 1];
            }
        }
    }
}

// ---------------- launch ------------------------------------------------------
extern "C" void kernel_launch(void* const* d_in, const int* in_sizes, int n_in,
                              void* d_out, int out_size) {
    const float* x   = (const float*)d_in[0];
    const int*   ei  = (const int*)d_in[1];
    const float* W0  = (const float*)d_in[2];
    const float* B0v = (const float*)d_in[3];
    const float* W1  = (const float*)d_in[4];
    const float* B1v = (const float*)d_in[5];
    const float* W2  = (const float*)d_in[6];
    const float* B2v = (const float*)d_in[7];
    const float* W3  = (const float*)d_in[8];
    const float* B3v = (const float*)d_in[9];
    float* out = (float*)d_out;

    k_zero<<<(NN + 255) / 256, 256>>>();
    k_hist<<<(EE + 255) / 256, 256>>>(ei);
    k_dinv<<<(NN + 255) / 256, 256>>>();
    k_scan<<<1, 1024>>>();
    k_scatter<<<(EE + 255) / 256, 256>>>(ei);
    k_copyx<<<4096, 256>>>(x);

    for (int k = 1; k < KMAX; k++)
        k_prop<<<NN, 288>>>(k);

    dim3 g(FOUT / BN, (NN + BM - 1) / BM, 4);
    k_gemm<<<g, 256>>>(W0, W1, W2, W3, B0v, B1v, B2v, B3v, out);
}

// round 3
// speedup vs baseline: 2.1890x; 2.1890x over previous
#include <cuda_runtime.h>
#include <cstdint>

#define NN   10000
#define EE   160000
#define FIN  1152
#define FOUT 288
#define KMAX 7
#define LDT  (KMAX*FIN)   /* 8064 */
#define LDT4 (LDT/4)      /* 2016 */

// ---------------- device scratch ----------------------------------------------
__device__ float4 g_T4[(size_t)KMAX * NN * (FIN/4)];   // T[node][k][f], ~322.6 MB
#define G_T ((float*)g_T4)

__device__ int   g_deg[NN];
__device__ float g_dinv[NN];
__device__ int   g_cnt[NN];
__device__ int   g_colptr[NN + 1];
__device__ int   g_cursor[NN];
__device__ int   g_src[EE];
__device__ float g_w[EE];

// ---------------- helpers -------------------------------------------------------
__device__ __forceinline__ uint32_t smem_u32(const void* p) {
    return (uint32_t)__cvta_generic_to_shared(p);
}
__device__ __forceinline__ void cp16(uint32_t s, const void* g) {
    asm volatile("cp.async.cg.shared.global [%0], [%1], 16;"
                 :: "r"(s), "l"(__cvta_generic_to_global(g)) : "memory");
}
__device__ __forceinline__ uint32_t f2tf(float x) {
    uint32_t r;
    asm("cvt.rna.tf32.f32 %0, %1;" : "=r"(r) : "f"(x));
    return r;
}
__device__ __forceinline__ void mma_tf32(float* d, const uint32_t* a, const uint32_t* b) {
    asm volatile(
        "mma.sync.aligned.m16n8k8.row.col.f32.tf32.tf32.f32 "
        "{%0,%1,%2,%3}, {%4,%5,%6,%7}, {%8,%9}, {%0,%1,%2,%3};"
        : "+f"(d[0]), "+f"(d[1]), "+f"(d[2]), "+f"(d[3])
        : "r"(a[0]), "r"(a[1]), "r"(a[2]), "r"(a[3]), "r"(b[0]), "r"(b[1]));
}

// ---------------- setup kernels ------------------------------------------------
__global__ void k_zero() {
    int i = blockIdx.x * blockDim.x + threadIdx.x;
    if (i < NN) { g_deg[i] = 0; g_cnt[i] = 0; g_cursor[i] = 0; }
}
__global__ void k_hist(const int* __restrict__ ei) {
    int e = blockIdx.x * blockDim.x + threadIdx.x;
    if (e < EE) {
        atomicAdd(&g_deg[ei[e]], 1);
        atomicAdd(&g_cnt[ei[EE + e]], 1);
    }
}
__global__ void k_dinv() {
    int i = blockIdx.x * blockDim.x + threadIdx.x;
    if (i < NN) {
        int d = g_deg[i];
        g_dinv[i] = (d > 0) ? rsqrtf((float)d) : 0.0f;
    }
}
__global__ void k_scan() {
    __shared__ int sh[1024];
    __shared__ int s_carry;
    const int tid = threadIdx.x;
    if (tid == 0) s_carry = 0;
    __syncthreads();
    for (int base = 0; base < NN; base += 1024) {
        int i = base + tid;
        int v = (i < NN) ? g_cnt[i] : 0;
        sh[tid] = v;
        __syncthreads();
        for (int off = 1; off < 1024; off <<= 1) {
            int tv = (tid >= off) ? sh[tid - off] : 0;
            __syncthreads();
            sh[tid] += tv;
            __syncthreads();
        }
        int carry = s_carry;
        if (i < NN) g_colptr[i] = carry + sh[tid] - v;
        __syncthreads();
        if (tid == 0) s_carry = carry + sh[1023];
        __syncthreads();
    }
    if (tid == 0) g_colptr[NN] = s_carry;
}
__global__ void k_scatter(const int* __restrict__ ei) {
    int e = blockIdx.x * blockDim.x + threadIdx.x;
    if (e < EE) {
        int r = ei[e];
        int c = ei[EE + e];
        int p = g_colptr[c] + atomicAdd(&g_cursor[c], 1);
        g_src[p] = r;
        g_w[p]   = -(g_dinv[r] * g_dinv[c]);
    }
}
__global__ void k_copyx(const float* __restrict__ x) {
    const int total = NN * (FIN / 4);
    for (int idx = blockIdx.x * blockDim.x + threadIdx.x; idx < total;
         idx += gridDim.x * blockDim.x) {
        int node = idx / (FIN / 4);
        int r    = idx - node * (FIN / 4);
        g_T4[(size_t)node * LDT4 + r] = ((const float4*)x)[idx];
    }
}

// ---------------- Chebyshev propagation ----------------------------------------
__global__ void k_prop(int kcur) {
    const int node = blockIdx.x;
    const int tid  = threadIdx.x;            // 288 threads, each owns a float4
    const int beg  = g_colptr[node];
    const int end  = g_colptr[node + 1];

    __shared__ int   ss[64];
    __shared__ float sw[64];

    float4 acc = make_float4(0.f, 0.f, 0.f, 0.f);
    const size_t foff  = (size_t)tid * 4;
    const size_t kprev = (size_t)(kcur - 1) * FIN;

    for (int b0 = beg; b0 < end; b0 += 64) {
        int cnt = min(64, end - b0);
        __syncthreads();
        if (tid < cnt) { ss[tid] = g_src[b0 + tid]; sw[tid] = g_w[b0 + tid]; }
        __syncthreads();
        for (int j = 0; j < cnt; j++) {
            float w = sw[j];
            const float4 v = *(const float4*)(G_T + (size_t)ss[j] * LDT + kprev + foff);
            acc.x += w * v.x; acc.y += w * v.y; acc.z += w * v.z; acc.w += w * v.w;
        }
    }

    const size_t nb = (size_t)node * LDT;
    float4 r;
    if (kcur == 1) {
        r = acc;
    } else {
        const float4 p = *(const float4*)(G_T + nb + (size_t)(kcur - 2) * FIN + foff);
        r.x = 2.f * acc.x - p.x; r.y = 2.f * acc.y - p.y;
        r.z = 2.f * acc.z - p.z; r.w = 2.f * acc.w - p.w;
    }
    *(float4*)(G_T + nb + (size_t)kcur * FIN + foff) = r;
}

// ---------------- tf32 mma.sync GEMM --------------------------------------------
// C[m0:m0+128, n0:n0+144] (conv c) = T[m0:m0+128, :KT] @ W_c[:KT, n0:n0+144]
// BM=128 BN=144 BK=16; 8 warps (4M x 2N); warp tile 32x72 = 2x9 m16n8k8 tiles.
#define BM 128
#define BN 144
#define BK 16
#define ASTR 20    /* padded A row stride (floats): banks (20m+k)%32 distinct */
#define BSTR 152   /* padded B row stride (floats): banks (152k+n)%32 distinct */

__global__ void __launch_bounds__(256, 2) k_gemm(
    const float* __restrict__ W0, const float* __restrict__ W1,
    const float* __restrict__ W2, const float* __restrict__ W3,
    const float* __restrict__ B0, const float* __restrict__ B1,
    const float* __restrict__ B2, const float* __restrict__ B3,
    float* __restrict__ out)
{
    __shared__ __align__(16) float As[2][BM * ASTR];   // 2 x 10240 B
    __shared__ __align__(16) float Bs[2][BK * BSTR];   // 2 x  9728 B

    const int c  = blockIdx.z;
    const int Kc = 4 + c;
    const int KT = Kc * FIN;
    const float* W  = (c == 0) ? W0 : (c == 1) ? W1 : (c == 2) ? W2 : W3;
    const float* Bv = (c == 0) ? B0 : (c == 1) ? B1 : (c == 2) ? B2 : B3;

    const int m0  = blockIdx.y * BM;
    const int n0  = blockIdx.x * BN;
    const int t   = threadIdx.x;
    const int lane = t & 31;
    const int wid  = t >> 5;
    const int warpM = wid >> 1;      // 0..3
    const int warpN = wid & 1;       // 0..1
    const int lq = lane >> 2;        // lane/4
    const int lr = lane & 3;         // lane%4

    // ---- staging coordinates ----
    // A: 512 float4 per tile; thread handles idx t and t+256
    const int ar0 = t >> 2, acc4 = (t & 3) * 4;
    int gm0 = m0 + ar0;      gm0 = (gm0 < NN) ? gm0 : (NN - 1);
    int gm1 = m0 + ar0 + 64; gm1 = (gm1 < NN) ? gm1 : (NN - 1);
    const float* a_src0 = G_T + (size_t)gm0 * LDT + acc4;
    const float* a_src1 = G_T + (size_t)gm1 * LDT + acc4;
    const uint32_t a_dst0 = smem_u32(&As[0][ar0 * ASTR + acc4]);
    const uint32_t a_dst1 = smem_u32(&As[0][(ar0 + 64) * ASTR + acc4]);
    const uint32_t abufo  = smem_u32(&As[1][0]) - smem_u32(&As[0][0]);

    // B: 576 float4 per tile; thread handles j = t, t+256, (t+512 if t<64)
    int brow[3], bc4[3];
#pragma unroll
    for (int i = 0; i < 3; i++) {
        int j = t + 256 * i;
        brow[i] = j / 36;
        bc4[i]  = (j % 36) * 4;
    }
    const bool b3 = (t < 64);
    uint32_t b_dst[3];
#pragma unroll
    for (int i = 0; i < 3; i++)
        b_dst[i] = smem_u32(&Bs[0][brow[i] * BSTR + bc4[i]]);
    const uint32_t bbufo = smem_u32(&Bs[1][0]) - smem_u32(&Bs[0][0]);

    float d[2][9][4];
#pragma unroll
    for (int i = 0; i < 2; i++)
#pragma unroll
        for (int j = 0; j < 9; j++)
#pragma unroll
            for (int q = 0; q < 4; q++) d[i][j][q] = 0.f;

    const int ntiles = KT / BK;

    // prologue: stage 0
    cp16(a_dst0, a_src0);
    cp16(a_dst1, a_src1);
    cp16(b_dst[0], W + (size_t)brow[0] * FOUT + n0 + bc4[0]);
    cp16(b_dst[1], W + (size_t)brow[1] * FOUT + n0 + bc4[1]);
    if (b3) cp16(b_dst[2], W + (size_t)brow[2] * FOUT + n0 + bc4[2]);
    asm volatile("cp.async.commit_group;" ::: "memory");

    for (int it = 0; it < ntiles; ++it) {
        const int cur = it & 1;
        if (it + 1 < ntiles) {
            const int k0 = (it + 1) * BK;
            const uint32_t ao = (cur ^ 1) ? abufo : 0u;
            const uint32_t bo = (cur ^ 1) ? bbufo : 0u;
            cp16(a_dst0 + ao, a_src0 + k0);
            cp16(a_dst1 + ao, a_src1 + k0);
            cp16(b_dst[0] + bo, W + (size_t)(k0 + brow[0]) * FOUT + n0 + bc4[0]);
            cp16(b_dst[1] + bo, W + (size_t)(k0 + brow[1]) * FOUT + n0 + bc4[1]);
            if (b3) cp16(b_dst[2] + bo, W + (size_t)(k0 + brow[2]) * FOUT + n0 + bc4[2]);
            asm volatile("cp.async.commit_group;" ::: "memory");
            asm volatile("cp.async.wait_group 1;" ::: "memory");
        } else {
            asm volatile("cp.async.wait_group 0;" ::: "memory");
        }
        __syncthreads();

        const float* As_ = As[cur];
        const float* Bs_ = Bs[cur];
#pragma unroll
        for (int ks = 0; ks < 2; ks++) {
            const int kb = ks * 8;
            uint32_t a[2][4];
#pragma unroll
            for (int mt = 0; mt < 2; mt++) {
                const int mrow = warpM * 32 + mt * 16 + lq;
                a[mt][0] = f2tf(As_[mrow * ASTR + kb + lr]);
                a[mt][1] = f2tf(As_[(mrow + 8) * ASTR + kb + lr]);
                a[mt][2] = f2tf(As_[mrow * ASTR + kb + lr + 4]);
                a[mt][3] = f2tf(As_[(mrow + 8) * ASTR + kb + lr + 4]);
            }
            uint32_t b[9][2];
#pragma unroll
            for (int nt = 0; nt < 9; nt++) {
                const int ncol = warpN * 72 + nt * 8 + lq;
                b[nt][0] = f2tf(Bs_[(kb + lr) * BSTR + ncol]);
                b[nt][1] = f2tf(Bs_[(kb + lr + 4) * BSTR + ncol]);
            }
#pragma unroll
            for (int mt = 0; mt < 2; mt++)
#pragma unroll
                for (int nt = 0; nt < 9; nt++)
                    mma_tf32(d[mt][nt], a[mt], b[nt]);
        }
        __syncthreads();
    }

    // epilogue: bias + store (float2 per fragment row)
#pragma unroll
    for (int mt = 0; mt < 2; mt++) {
        const int row0 = m0 + warpM * 32 + mt * 16 + lq;
        const int row1 = row0 + 8;
#pragma unroll
        for (int nt = 0; nt < 9; nt++) {
            const int col = warpN * 72 + nt * 8 + lr * 2;
            const float bx = __ldg(&Bv[n0 + col]);
            const float by = __ldg(&Bv[n0 + col + 1]);
            const size_t oc = (size_t)c * FOUT + n0 + col;
            if (row0 < NN) {
                float2 v = make_float2(d[mt][nt][0] + bx, d[mt][nt][1] + by);
                *(float2*)&out[(size_t)row0 * 1152 + oc] = v;
            }
            if (row1 < NN) {
                float2 v = make_float2(d[mt][nt][2] + bx, d[mt][nt][3] + by);
                *(float2*)&out[(size_t)row1 * 1152 + oc] = v;
            }
        }
    }
}

// ---------------- launch --------------------------------------------------------
extern "C" void kernel_launch(void* const* d_in, const int* in_sizes, int n_in,
                              void* d_out, int out_size) {
    const float* x   = (const float*)d_in[0];
    const int*   ei  = (const int*)d_in[1];
    const float* W0  = (const float*)d_in[2];
    const float* B0v = (const float*)d_in[3];
    const float* W1  = (const float*)d_in[4];
    const float* B1v = (const float*)d_in[5];
    const float* W2  = (const float*)d_in[6];
    const float* B2v = (const float*)d_in[7];
    const float* W3  = (const float*)d_in[8];
    const float* B3v = (const float*)d_in[9];
    float* out = (float*)d_out;

    k_zero<<<(NN + 255) / 256, 256>>>();
    k_hist<<<(EE + 255) / 256, 256>>>(ei);
    k_dinv<<<(NN + 255) / 256, 256>>>();
    k_scan<<<1, 1024>>>();
    k_scatter<<<(EE + 255) / 256, 256>>>(ei);
    k_copyx<<<4096, 256>>>(x);

    for (int k = 1; k < KMAX; k++)
        k_prop<<<NN, 288>>>(k);

    dim3 g(FOUT / BN, (NN + BM - 1) / BM, 4);
    k_gemm<<<g, 256>>>(W0, W1, W2, W3, B0v, B1v, B2v, B3v, out);
}

// round 4
// speedup vs baseline: 2.5362x; 1.1586x over previous
#include <cuda_runtime.h>
#include <cstdint>

#define NN   10000
#define EE   160000
#define FIN  1152
#define FOUT 288
#define KMAX 7
#define LDT  (KMAX*FIN)   /* 8064 */
#define LDT4 (LDT/4)      /* 2016 */

// ---------------- device scratch ----------------------------------------------
__device__ float4 g_T4[(size_t)KMAX * NN * (FIN/4)];   // fp32 T (recurrence)
#define G_T ((float*)g_T4)
__device__ float4 g_Tr4[(size_t)KMAX * NN * (FIN/4)];  // tf32-rounded T (GEMM A)
#define G_TR ((float*)g_Tr4)

__device__ int   g_deg[NN];
__device__ float g_dinv[NN];
__device__ int   g_cnt[NN];
__device__ int   g_colptr[NN + 1];
__device__ int   g_cursor[NN];
__device__ int   g_src[EE];
__device__ float g_w[EE];

// tf32-rounded W, native layout [k][n] per conv, packed
#define WR_OFF0 0
#define WR_OFF1 (4*FIN*FOUT)
#define WR_OFF2 (WR_OFF1 + 5*FIN*FOUT)
#define WR_OFF3 (WR_OFF2 + 6*FIN*FOUT)
#define WR_TOT  (WR_OFF3 + 7*FIN*FOUT)
__device__ float g_Wr[WR_TOT];

// ---------------- helpers -------------------------------------------------------
__device__ __forceinline__ uint32_t smem_u32(const void* p) {
    return (uint32_t)__cvta_generic_to_shared(p);
}
__device__ __forceinline__ void cp16(uint32_t s, const void* g) {
    asm volatile("cp.async.cg.shared.global [%0], [%1], 16;"
                 :: "r"(s), "l"(__cvta_generic_to_global(g)) : "memory");
}
__device__ __forceinline__ float f2tf_f(float x) {
    uint32_t r;
    asm("cvt.rna.tf32.f32 %0, %1;" : "=r"(r) : "f"(x));
    return __uint_as_float(r);
}
__device__ __forceinline__ void mma_tf32(float* d, const uint32_t* a, const uint32_t* b) {
    asm volatile(
        "mma.sync.aligned.m16n8k8.row.col.f32.tf32.tf32.f32 "
        "{%0,%1,%2,%3}, {%4,%5,%6,%7}, {%8,%9}, {%0,%1,%2,%3};"
        : "+f"(d[0]), "+f"(d[1]), "+f"(d[2]), "+f"(d[3])
        : "r"(a[0]), "r"(a[1]), "r"(a[2]), "r"(a[3]), "r"(b[0]), "r"(b[1]));
}

// ---------------- setup kernels ------------------------------------------------
__global__ void k_zero() {
    int i = blockIdx.x * blockDim.x + threadIdx.x;
    if (i < NN) { g_deg[i] = 0; g_cnt[i] = 0; g_cursor[i] = 0; }
}
__global__ void k_hist(const int* __restrict__ ei) {
    int e = blockIdx.x * blockDim.x + threadIdx.x;
    if (e < EE) {
        atomicAdd(&g_deg[ei[e]], 1);
        atomicAdd(&g_cnt[ei[EE + e]], 1);
    }
}
__global__ void k_dinv() {
    int i = blockIdx.x * blockDim.x + threadIdx.x;
    if (i < NN) {
        int d = g_deg[i];
        g_dinv[i] = (d > 0) ? rsqrtf((float)d) : 0.0f;
    }
}
// 1024-thread scan, 10 elems/thread, shfl-based
__global__ void k_scan() {
    __shared__ int wsum[32];
    const int tid  = threadIdx.x;
    const int lane = tid & 31;
    const int warp = tid >> 5;

    int v[10];
    int s = 0;
#pragma unroll
    for (int i = 0; i < 10; i++) {
        int idx = tid * 10 + i;
        v[i] = (idx < NN) ? g_cnt[idx] : 0;
        s += v[i];
    }
    int inc = s;
#pragma unroll
    for (int off = 1; off < 32; off <<= 1) {
        int n = __shfl_up_sync(0xFFFFFFFF, inc, off);
        if (lane >= off) inc += n;
    }
    if (lane == 31) wsum[warp] = inc;
    __syncthreads();
    if (warp == 0) {
        int w = wsum[lane];
#pragma unroll
        for (int off = 1; off < 32; off <<= 1) {
            int n = __shfl_up_sync(0xFFFFFFFF, w, off);
            if (lane >= off) w += n;
        }
        wsum[lane] = w;
    }
    __syncthreads();
    int base = (warp > 0 ? wsum[warp - 1] : 0) + inc - s;  // exclusive prefix
#pragma unroll
    for (int i = 0; i < 10; i++) {
        int idx = tid * 10 + i;
        if (idx < NN) g_colptr[idx] = base;
        base += v[i];
    }
    if (tid == 1023) g_colptr[NN] = wsum[31];
}
__global__ void k_scatter(const int* __restrict__ ei) {
    int e = blockIdx.x * blockDim.x + threadIdx.x;
    if (e < EE) {
        int r = ei[e];
        int c = ei[EE + e];
        int p = g_colptr[c] + atomicAdd(&g_cursor[c], 1);
        g_src[p] = r;
        g_w[p]   = -(g_dinv[r] * g_dinv[c]);
    }
}
__global__ void k_copyx(const float* __restrict__ x) {
    const int total = NN * (FIN / 4);
    for (int idx = blockIdx.x * blockDim.x + threadIdx.x; idx < total;
         idx += gridDim.x * blockDim.x) {
        int node = idx / (FIN / 4);
        int r    = idx - node * (FIN / 4);
        float4 v = ((const float4*)x)[idx];
        g_T4[(size_t)node * LDT4 + r] = v;
        float4 t;
        t.x = f2tf_f(v.x); t.y = f2tf_f(v.y); t.z = f2tf_f(v.z); t.w = f2tf_f(v.w);
        g_Tr4[(size_t)node * LDT4 + r] = t;
    }
}
__global__ void k_wround(const float* __restrict__ W, int off, int n) {
    int i = blockIdx.x * blockDim.x + threadIdx.x;
    if (i < n) g_Wr[off + i] = f2tf_f(W[i]);
}

// ---------------- Chebyshev propagation ----------------------------------------
__global__ void k_prop(int kcur) {
    const int node = blockIdx.x;
    const int tid  = threadIdx.x;            // 288 threads, each owns a float4
    const int beg  = g_colptr[node];
    const int end  = g_colptr[node + 1];

    __shared__ int   ss[64];
    __shared__ float sw[64];

    float4 acc = make_float4(0.f, 0.f, 0.f, 0.f);
    const size_t foff  = (size_t)tid * 4;
    const size_t kprev = (size_t)(kcur - 1) * FIN;

    for (int b0 = beg; b0 < end; b0 += 64) {
        int cnt = min(64, end - b0);
        __syncthreads();
        if (tid < cnt) { ss[tid] = g_src[b0 + tid]; sw[tid] = g_w[b0 + tid]; }
        __syncthreads();
        for (int j = 0; j < cnt; j++) {
            float w = sw[j];
            const float4 v = *(const float4*)(G_T + (size_t)ss[j] * LDT + kprev + foff);
            acc.x += w * v.x; acc.y += w * v.y; acc.z += w * v.z; acc.w += w * v.w;
        }
    }

    const size_t nb = (size_t)node * LDT;
    float4 r;
    if (kcur == 1) {
        r = acc;
    } else {
        const float4 p = *(const float4*)(G_T + nb + (size_t)(kcur - 2) * FIN + foff);
        r.x = 2.f * acc.x - p.x; r.y = 2.f * acc.y - p.y;
        r.z = 2.f * acc.z - p.z; r.w = 2.f * acc.w - p.w;
    }
    const size_t pos = nb + (size_t)kcur * FIN + foff;
    *(float4*)(G_T + pos) = r;
    float4 t;
    t.x = f2tf_f(r.x); t.y = f2tf_f(r.y); t.z = f2tf_f(r.z); t.w = f2tf_f(r.w);
    *(float4*)(G_TR + pos) = t;
}

// ---------------- tf32 mma.sync GEMM --------------------------------------------
// 128 threads, 4 warps (2M x 2N), warp tile 64x72 (mt=4, nt=9).
// Operands pre-rounded to tf32 in g_Tr / g_Wr -> no CVT in mainloop.
#define BM 128
#define BN 144
#define BK 16
#define ASTR 20
#define BSTR 152

__global__ void __launch_bounds__(128, 2) k_gemm(
    const float* __restrict__ B0, const float* __restrict__ B1,
    const float* __restrict__ B2, const float* __restrict__ B3,
    float* __restrict__ out)
{
    __shared__ __align__(16) float As[2][BM * ASTR];   // 2 x 10240 B
    __shared__ __align__(16) float Bs[2][BK * BSTR];   // 2 x  9728 B

    const int c  = blockIdx.x & 3;
    const int nb = blockIdx.x >> 2;
    const int Kc = 4 + c;
    const int KT = Kc * FIN;
    const int woff = (c == 0) ? WR_OFF0 : (c == 1) ? WR_OFF1 : (c == 2) ? WR_OFF2 : WR_OFF3;
    const float* W  = g_Wr + woff;
    const float* Bv = (c == 0) ? B0 : (c == 1) ? B1 : (c == 2) ? B2 : B3;

    const int m0  = blockIdx.y * BM;
    const int n0  = nb * BN;
    const int t   = threadIdx.x;
    const int lane = t & 31;
    const int wid  = t >> 5;
    const int warpM = wid >> 1;      // 0..1
    const int warpN = wid & 1;       // 0..1
    const int lq = lane >> 2;
    const int lr = lane & 3;

    // ---- staging coordinates ----
    // A: 512 float4; thread handles idx t + 128*i, i<4
    const int ar0 = t >> 2, acc4 = (t & 3) * 4;   // idx=t -> row t>>2; +128 -> +32 rows
    const float* a_src[4];
    uint32_t a_dst[4];
#pragma unroll
    for (int i = 0; i < 4; i++) {
        int row = ar0 + 32 * i;
        int gm = m0 + row; gm = (gm < NN) ? gm : (NN - 1);
        a_src[i] = G_TR + (size_t)gm * LDT + acc4;
        a_dst[i] = smem_u32(&As[0][row * ASTR + acc4]);
    }
    const uint32_t abufo = smem_u32(&As[1][0]) - smem_u32(&As[0][0]);

    // B: 576 float4; thread handles idx t + 128*i, i<4, plus 512+t if t<64
    int brow[5], bc4[5];
#pragma unroll
    for (int i = 0; i < 5; i++) {
        int j = t + 128 * i;
        brow[i] = j / 36;
        bc4[i]  = (j % 36) * 4;
    }
    const bool b5 = (t < 64);
    uint32_t b_dst[5];
#pragma unroll
    for (int i = 0; i < 5; i++)
        b_dst[i] = smem_u32(&Bs[0][brow[i] * BSTR + bc4[i]]);
    const uint32_t bbufo = smem_u32(&Bs[1][0]) - smem_u32(&Bs[0][0]);

    float d[4][9][4];
#pragma unroll
    for (int i = 0; i < 4; i++)
#pragma unroll
        for (int j = 0; j < 9; j++)
#pragma unroll
            for (int q = 0; q < 4; q++) d[i][j][q] = 0.f;

    const int ntiles = KT / BK;

    // prologue: stage 0
#pragma unroll
    for (int i = 0; i < 4; i++) cp16(a_dst[i], a_src[i]);
#pragma unroll
    for (int i = 0; i < 4; i++)
        cp16(b_dst[i], W + (size_t)brow[i] * FOUT + n0 + bc4[i]);
    if (b5) cp16(b_dst[4], W + (size_t)brow[4] * FOUT + n0 + bc4[4]);
    asm volatile("cp.async.commit_group;" ::: "memory");

    for (int it = 0; it < ntiles; ++it) {
        const int cur = it & 1;
        if (it + 1 < ntiles) {
            const int k0 = (it + 1) * BK;
            const uint32_t ao = (cur ^ 1) ? abufo : 0u;
            const uint32_t bo = (cur ^ 1) ? bbufo : 0u;
#pragma unroll
            for (int i = 0; i < 4; i++) cp16(a_dst[i] + ao, a_src[i] + k0);
#pragma unroll
            for (int i = 0; i < 4; i++)
                cp16(b_dst[i] + bo, W + (size_t)(k0 + brow[i]) * FOUT + n0 + bc4[i]);
            if (b5) cp16(b_dst[4] + bo, W + (size_t)(k0 + brow[4]) * FOUT + n0 + bc4[4]);
            asm volatile("cp.async.commit_group;" ::: "memory");
            asm volatile("cp.async.wait_group 1;" ::: "memory");
        } else {
            asm volatile("cp.async.wait_group 0;" ::: "memory");
        }
        __syncthreads();

        const float* As_ = As[cur];
        const float* Bs_ = Bs[cur];
#pragma unroll
        for (int ks = 0; ks < 2; ks++) {
            const int kb = ks * 8;
            uint32_t a[4][4];
#pragma unroll
            for (int mt = 0; mt < 4; mt++) {
                const int mrow = warpM * 64 + mt * 16 + lq;
                a[mt][0] = __float_as_uint(As_[mrow * ASTR + kb + lr]);
                a[mt][1] = __float_as_uint(As_[(mrow + 8) * ASTR + kb + lr]);
                a[mt][2] = __float_as_uint(As_[mrow * ASTR + kb + lr + 4]);
                a[mt][3] = __float_as_uint(As_[(mrow + 8) * ASTR + kb + lr + 4]);
            }
            uint32_t b[9][2];
#pragma unroll
            for (int nt = 0; nt < 9; nt++) {
                const int ncol = warpN * 72 + nt * 8 + lq;
                b[nt][0] = __float_as_uint(Bs_[(kb + lr) * BSTR + ncol]);
                b[nt][1] = __float_as_uint(Bs_[(kb + lr + 4) * BSTR + ncol]);
            }
#pragma unroll
            for (int mt = 0; mt < 4; mt++)
#pragma unroll
                for (int nt = 0; nt < 9; nt++)
                    mma_tf32(d[mt][nt], a[mt], b[nt]);
        }
        __syncthreads();
    }

    // epilogue: bias + store
#pragma unroll
    for (int mt = 0; mt < 4; mt++) {
        const int row0 = m0 + warpM * 64 + mt * 16 + lq;
        const int row1 = row0 + 8;
#pragma unroll
        for (int nt = 0; nt < 9; nt++) {
            const int col = warpN * 72 + nt * 8 + lr * 2;
            const float bx = __ldg(&Bv[n0 + col]);
            const float by = __ldg(&Bv[n0 + col + 1]);
            const size_t oc = (size_t)c * FOUT + n0 + col;
            if (row0 < NN) {
                float2 v = make_float2(d[mt][nt][0] + bx, d[mt][nt][1] + by);
                *(float2*)&out[(size_t)row0 * 1152 + oc] = v;
            }
            if (row1 < NN) {
                float2 v = make_float2(d[mt][nt][2] + bx, d[mt][nt][3] + by);
                *(float2*)&out[(size_t)row1 * 1152 + oc] = v;
            }
        }
    }
}

// ---------------- launch --------------------------------------------------------
extern "C" void kernel_launch(void* const* d_in, const int* in_sizes, int n_in,
                              void* d_out, int out_size) {
    const float* x   = (const float*)d_in[0];
    const int*   ei  = (const int*)d_in[1];
    const float* W0  = (const float*)d_in[2];
    const float* B0v = (const float*)d_in[3];
    const float* W1  = (const float*)d_in[4];
    const float* B1v = (const float*)d_in[5];
    const float* W2  = (const float*)d_in[6];
    const float* B2v = (const float*)d_in[7];
    const float* W3  = (const float*)d_in[8];
    const float* B3v = (const float*)d_in[9];
    float* out = (float*)d_out;

    k_zero<<<(NN + 255) / 256, 256>>>();
    k_hist<<<(EE + 255) / 256, 256>>>(ei);
    k_dinv<<<(NN + 255) / 256, 256>>>();
    k_scan<<<1, 1024>>>();
    k_scatter<<<(EE + 255) / 256, 256>>>(ei);
    k_copyx<<<4096, 256>>>(x);

    k_wround<<<(4 * FIN * FOUT + 255) / 256, 256>>>(W0, WR_OFF0, 4 * FIN * FOUT);
    k_wround<<<(5 * FIN * FOUT + 255) / 256, 256>>>(W1, WR_OFF1, 5 * FIN * FOUT);
    k_wround<<<(6 * FIN * FOUT + 255) / 256, 256>>>(W2, WR_OFF2, 6 * FIN * FOUT);
    k_wround<<<(7 * FIN * FOUT + 255) / 256, 256>>>(W3, WR_OFF3, 7 * FIN * FOUT);

    for (int k = 1; k < KMAX; k++)
        k_prop<<<NN, 288>>>(k);

    dim3 g(4 * (FOUT / BN), (NN + BM - 1) / BM);
    k_gemm<<<g, 128>>>(B0v, B1v, B2v, B3v, out);
}

// round 5
// speedup vs baseline: 2.6045x; 1.0269x over previous
#include <cuda_runtime.h>
#include <cstdint>

#define NN   10000
#define EE   160000
#define FIN  1152
#define FOUT 288
#define KMAX 7
#define LDT  (KMAX*FIN)   /* 8064 */
#define LDT4 (LDT/4)      /* 2016 */

// ---------------- device scratch ----------------------------------------------
__device__ float4 g_T4[(size_t)KMAX * NN * (FIN/4)];   // fp32 T (recurrence)
#define G_T ((float*)g_T4)
__device__ float4 g_Tr4[(size_t)KMAX * NN * (FIN/4)];  // tf32-rounded T (GEMM A)
#define G_TR ((float*)g_Tr4)

__device__ int   g_deg[NN];
__device__ float g_dinv[NN];
__device__ int   g_cnt[NN];
__device__ int   g_colptr[NN + 1];
__device__ int   g_cursor[NN];
__device__ int   g_src[EE];
__device__ float g_w[EE];

// tf32-rounded W, native layout [k][n] per conv, packed
#define WR_OFF0 0
#define WR_OFF1 (4*FIN*FOUT)
#define WR_OFF2 (WR_OFF1 + 5*FIN*FOUT)
#define WR_OFF3 (WR_OFF2 + 6*FIN*FOUT)
#define WR_TOT  (WR_OFF3 + 7*FIN*FOUT)
__device__ float g_Wr[WR_TOT];

// ---------------- helpers -------------------------------------------------------
__device__ __forceinline__ uint32_t smem_u32(const void* p) {
    return (uint32_t)__cvta_generic_to_shared(p);
}
__device__ __forceinline__ void cp16(uint32_t s, const void* g) {
    asm volatile("cp.async.cg.shared.global [%0], [%1], 16;"
                 :: "r"(s), "l"(__cvta_generic_to_global(g)) : "memory");
}
__device__ __forceinline__ float f2tf_f(float x) {
    uint32_t r;
    asm("cvt.rna.tf32.f32 %0, %1;" : "=r"(r) : "f"(x));
    return __uint_as_float(r);
}
__device__ __forceinline__ void mma_tf32(float* d, const uint32_t* a, const uint32_t* b) {
    asm volatile(
        "mma.sync.aligned.m16n8k8.row.col.f32.tf32.tf32.f32 "
        "{%0,%1,%2,%3}, {%4,%5,%6,%7}, {%8,%9}, {%0,%1,%2,%3};"
        : "+f"(d[0]), "+f"(d[1]), "+f"(d[2]), "+f"(d[3])
        : "r"(a[0]), "r"(a[1]), "r"(a[2]), "r"(a[3]), "r"(b[0]), "r"(b[1]));
}

// ---------------- setup kernels ------------------------------------------------
__global__ void k_zero() {
    int i = blockIdx.x * blockDim.x + threadIdx.x;
    if (i < NN) { g_deg[i] = 0; g_cnt[i] = 0; g_cursor[i] = 0; }
}
__global__ void k_hist(const int* __restrict__ ei) {
    int e = blockIdx.x * blockDim.x + threadIdx.x;
    if (e < EE) {
        atomicAdd(&g_deg[ei[e]], 1);
        atomicAdd(&g_cnt[ei[EE + e]], 1);
    }
}
__global__ void k_dinv() {
    int i = blockIdx.x * blockDim.x + threadIdx.x;
    if (i < NN) {
        int d = g_deg[i];
        g_dinv[i] = (d > 0) ? rsqrtf((float)d) : 0.0f;
    }
}
__global__ void k_scan() {
    __shared__ int wsum[32];
    const int tid  = threadIdx.x;
    const int lane = tid & 31;
    const int warp = tid >> 5;

    int v[10];
    int s = 0;
#pragma unroll
    for (int i = 0; i < 10; i++) {
        int idx = tid * 10 + i;
        v[i] = (idx < NN) ? g_cnt[idx] : 0;
        s += v[i];
    }
    int inc = s;
#pragma unroll
    for (int off = 1; off < 32; off <<= 1) {
        int n = __shfl_up_sync(0xFFFFFFFF, inc, off);
        if (lane >= off) inc += n;
    }
    if (lane == 31) wsum[warp] = inc;
    __syncthreads();
    if (warp == 0) {
        int w = wsum[lane];
#pragma unroll
        for (int off = 1; off < 32; off <<= 1) {
            int n = __shfl_up_sync(0xFFFFFFFF, w, off);
            if (lane >= off) w += n;
        }
        wsum[lane] = w;
    }
    __syncthreads();
    int base = (warp > 0 ? wsum[warp - 1] : 0) + inc - s;
#pragma unroll
    for (int i = 0; i < 10; i++) {
        int idx = tid * 10 + i;
        if (idx < NN) g_colptr[idx] = base;
        base += v[i];
    }
    if (tid == 1023) g_colptr[NN] = wsum[31];
}
__global__ void k_scatter(const int* __restrict__ ei) {
    int e = blockIdx.x * blockDim.x + threadIdx.x;
    if (e < EE) {
        int r = ei[e];
        int c = ei[EE + e];
        int p = g_colptr[c] + atomicAdd(&g_cursor[c], 1);
        g_src[p] = r;
        g_w[p]   = -(g_dinv[r] * g_dinv[c]);
    }
}
__global__ void k_copyx(const float* __restrict__ x) {
    const int total = NN * (FIN / 4);
    for (int idx = blockIdx.x * blockDim.x + threadIdx.x; idx < total;
         idx += gridDim.x * blockDim.x) {
        int node = idx / (FIN / 4);
        int r    = idx - node * (FIN / 4);
        float4 v = ((const float4*)x)[idx];
        g_T4[(size_t)node * LDT4 + r] = v;
        float4 t;
        t.x = f2tf_f(v.x); t.y = f2tf_f(v.y); t.z = f2tf_f(v.z); t.w = f2tf_f(v.w);
        g_Tr4[(size_t)node * LDT4 + r] = t;
    }
}
__global__ void k_wround(const float* __restrict__ W, int off, int n) {
    int i = blockIdx.x * blockDim.x + threadIdx.x;
    if (i < n) g_Wr[off + i] = f2tf_f(W[i]);
}

// ---------------- Chebyshev propagation ----------------------------------------
__global__ void k_prop(int kcur) {
    const int node = blockIdx.x;
    const int tid  = threadIdx.x;
    const int beg  = g_colptr[node];
    const int end  = g_colptr[node + 1];

    __shared__ int   ss[64];
    __shared__ float sw[64];

    float4 acc = make_float4(0.f, 0.f, 0.f, 0.f);
    const size_t foff  = (size_t)tid * 4;
    const size_t kprev = (size_t)(kcur - 1) * FIN;

    for (int b0 = beg; b0 < end; b0 += 64) {
        int cnt = min(64, end - b0);
        __syncthreads();
        if (tid < cnt) { ss[tid] = g_src[b0 + tid]; sw[tid] = g_w[b0 + tid]; }
        __syncthreads();
        for (int j = 0; j < cnt; j++) {
            float w = sw[j];
            const float4 v = *(const float4*)(G_T + (size_t)ss[j] * LDT + kprev + foff);
            acc.x += w * v.x; acc.y += w * v.y; acc.z += w * v.z; acc.w += w * v.w;
        }
    }

    const size_t nb = (size_t)node * LDT;
    float4 r;
    if (kcur == 1) {
        r = acc;
    } else {
        const float4 p = *(const float4*)(G_T + nb + (size_t)(kcur - 2) * FIN + foff);
        r.x = 2.f * acc.x - p.x; r.y = 2.f * acc.y - p.y;
        r.z = 2.f * acc.z - p.z; r.w = 2.f * acc.w - p.w;
    }
    const size_t pos = nb + (size_t)kcur * FIN + foff;
    if (kcur < KMAX - 1) *(float4*)(G_T + pos) = r;   // fp32 T only needed for next props
    float4 t;
    t.x = f2tf_f(r.x); t.y = f2tf_f(r.y); t.z = f2tf_f(r.z); t.w = f2tf_f(r.w);
    *(float4*)(G_TR + pos) = t;
}

// ---------------- tf32 mma.sync GEMM (4-stage cp.async pipeline) -----------------
#define BM 128
#define BN 144
#define BK 16
#define ASTR 20
#define BSTR 152
#define STAGES 4
#define A_ST (BM*ASTR)          /* floats per A stage: 2560 */
#define B_ST (BK*BSTR)          /* floats per B stage: 2432 */
#define SMEM_GEMM ((STAGES*(A_ST+B_ST))*4)   /* 79872 B */

__global__ void __launch_bounds__(128, 2) k_gemm(
    const float* __restrict__ B0, const float* __restrict__ B1,
    const float* __restrict__ B2, const float* __restrict__ B3,
    float* __restrict__ out)
{
    extern __shared__ __align__(16) float smp[];
    float* Abase = smp;
    float* Bbase = smp + STAGES * A_ST;

    const int c  = 3 - (blockIdx.x & 3);          // heavy convs first
    const int nb = blockIdx.x >> 2;
    const int Kc = 4 + c;
    const int KT = Kc * FIN;
    const int woff = (c == 0) ? WR_OFF0 : (c == 1) ? WR_OFF1 : (c == 2) ? WR_OFF2 : WR_OFF3;
    const float* W  = g_Wr + woff;
    const float* Bv = (c == 0) ? B0 : (c == 1) ? B1 : (c == 2) ? B2 : B3;

    const int m0  = blockIdx.y * BM;
    const int n0  = nb * BN;
    const int t   = threadIdx.x;
    const int lane = t & 31;
    const int wid  = t >> 5;
    const int warpM = wid >> 1;
    const int warpN = wid & 1;
    const int lq = lane >> 2;
    const int lr = lane & 3;

    // ---- staging coordinates ----
    const int ar0 = t >> 2, acc4 = (t & 3) * 4;
    const float* a_src[4];
    uint32_t a_dst[4];
#pragma unroll
    for (int i = 0; i < 4; i++) {
        int row = ar0 + 32 * i;
        int gm = m0 + row; gm = (gm < NN) ? gm : (NN - 1);
        a_src[i] = G_TR + (size_t)gm * LDT + acc4;
        a_dst[i] = smem_u32(&Abase[row * ASTR + acc4]);
    }
    int brow[5], bc4[5];
#pragma unroll
    for (int i = 0; i < 5; i++) {
        int j = t + 128 * i;
        brow[i] = j / 36;
        bc4[i]  = (j % 36) * 4;
    }
    const bool b5 = (t < 64);
    uint32_t b_dst[5];
#pragma unroll
    for (int i = 0; i < 5; i++)
        b_dst[i] = smem_u32(&Bbase[brow[i] * BSTR + bc4[i]]);

    float d[4][9][4];
#pragma unroll
    for (int i = 0; i < 4; i++)
#pragma unroll
        for (int j = 0; j < 9; j++)
#pragma unroll
            for (int q = 0; q < 4; q++) d[i][j][q] = 0.f;

    const int ntiles = KT / BK;

    // prologue: stages 0..2
#pragma unroll
    for (int s = 0; s < STAGES - 1; s++) {
        const int k0 = s * BK;
        const uint32_t ao = s * (A_ST * 4);
        const uint32_t bo = s * (B_ST * 4);
#pragma unroll
        for (int i = 0; i < 4; i++) cp16(a_dst[i] + ao, a_src[i] + k0);
#pragma unroll
        for (int i = 0; i < 4; i++)
            cp16(b_dst[i] + bo, W + (size_t)(k0 + brow[i]) * FOUT + n0 + bc4[i]);
        if (b5) cp16(b_dst[4] + bo, W + (size_t)(k0 + brow[4]) * FOUT + n0 + bc4[4]);
        asm volatile("cp.async.commit_group;" ::: "memory");
    }

    for (int it = 0; it < ntiles; ++it) {
        asm volatile("cp.async.wait_group %0;" :: "n"(STAGES - 2) : "memory");
        __syncthreads();

        // issue tile it+3 into the stage freed by compute(it-1)
        {
            const int ld = it + STAGES - 1;
            if (ld < ntiles) {
                const int s = ld & (STAGES - 1);
                const int k0 = ld * BK;
                const uint32_t ao = s * (A_ST * 4);
                const uint32_t bo = s * (B_ST * 4);
#pragma unroll
                for (int i = 0; i < 4; i++) cp16(a_dst[i] + ao, a_src[i] + k0);
#pragma unroll
                for (int i = 0; i < 4; i++)
                    cp16(b_dst[i] + bo, W + (size_t)(k0 + brow[i]) * FOUT + n0 + bc4[i]);
                if (b5) cp16(b_dst[4] + bo, W + (size_t)(k0 + brow[4]) * FOUT + n0 + bc4[4]);
            }
            asm volatile("cp.async.commit_group;" ::: "memory");  // uniform group count
        }

        const float* As_ = Abase + (it & (STAGES - 1)) * A_ST;
        const float* Bs_ = Bbase + (it & (STAGES - 1)) * B_ST;
#pragma unroll
        for (int ks = 0; ks < 2; ks++) {
            const int kb = ks * 8;
            uint32_t a[4][4];
#pragma unroll
            for (int mt = 0; mt < 4; mt++) {
                const int mrow = warpM * 64 + mt * 16 + lq;
                a[mt][0] = __float_as_uint(As_[mrow * ASTR + kb + lr]);
                a[mt][1] = __float_as_uint(As_[(mrow + 8) * ASTR + kb + lr]);
                a[mt][2] = __float_as_uint(As_[mrow * ASTR + kb + lr + 4]);
                a[mt][3] = __float_as_uint(As_[(mrow + 8) * ASTR + kb + lr + 4]);
            }
            uint32_t b[9][2];
#pragma unroll
            for (int nt = 0; nt < 9; nt++) {
                const int ncol = warpN * 72 + nt * 8 + lq;
                b[nt][0] = __float_as_uint(Bs_[(kb + lr) * BSTR + ncol]);
                b[nt][1] = __float_as_uint(Bs_[(kb + lr + 4) * BSTR + ncol]);
            }
#pragma unroll
            for (int mt = 0; mt < 4; mt++)
#pragma unroll
                for (int nt = 0; nt < 9; nt++)
                    mma_tf32(d[mt][nt], a[mt], b[nt]);
        }
    }

    // epilogue: bias + store
#pragma unroll
    for (int mt = 0; mt < 4; mt++) {
        const int row0 = m0 + warpM * 64 + mt * 16 + lq;
        const int row1 = row0 + 8;
#pragma unroll
        for (int nt = 0; nt < 9; nt++) {
            const int col = warpN * 72 + nt * 8 + lr * 2;
            const float bx = __ldg(&Bv[n0 + col]);
            const float by = __ldg(&Bv[n0 + col + 1]);
            const size_t oc = (size_t)c * FOUT + n0 + col;
            if (row0 < NN) {
                float2 v = make_float2(d[mt][nt][0] + bx, d[mt][nt][1] + by);
                *(float2*)&out[(size_t)row0 * 1152 + oc] = v;
            }
            if (row1 < NN) {
                float2 v = make_float2(d[mt][nt][2] + bx, d[mt][nt][3] + by);
                *(float2*)&out[(size_t)row1 * 1152 + oc] = v;
            }
        }
    }
}

// ---------------- launch --------------------------------------------------------
extern "C" void kernel_launch(void* const* d_in, const int* in_sizes, int n_in,
                              void* d_out, int out_size) {
    const float* x   = (const float*)d_in[0];
    const int*   ei  = (const int*)d_in[1];
    const float* W0  = (const float*)d_in[2];
    const float* B0v = (const float*)d_in[3];
    const float* W1  = (const float*)d_in[4];
    const float* B1v = (const float*)d_in[5];
    const float* W2  = (const float*)d_in[6];
    const float* B2v = (const float*)d_in[7];
    const float* W3  = (const float*)d_in[8];
    const float* B3v = (const float*)d_in[9];
    float* out = (float*)d_out;

    cudaFuncSetAttribute(k_gemm, cudaFuncAttributeMaxDynamicSharedMemorySize, SMEM_GEMM);

    k_zero<<<(NN + 255) / 256, 256>>>();
    k_hist<<<(EE + 255) / 256, 256>>>(ei);
    k_dinv<<<(NN + 255) / 256, 256>>>();
    k_scan<<<1, 1024>>>();
    k_scatter<<<(EE + 255) / 256, 256>>>(ei);
    k_copyx<<<4096, 256>>>(x);

    k_wround<<<(4 * FIN * FOUT + 255) / 256, 256>>>(W0, WR_OFF0, 4 * FIN * FOUT);
    k_wround<<<(5 * FIN * FOUT + 255) / 256, 256>>>(W1, WR_OFF1, 5 * FIN * FOUT);
    k_wround<<<(6 * FIN * FOUT + 255) / 256, 256>>>(W2, WR_OFF2, 6 * FIN * FOUT);
    k_wround<<<(7 * FIN * FOUT + 255) / 256, 256>>>(W3, WR_OFF3, 7 * FIN * FOUT);

    for (int k = 1; k < KMAX; k++)
        k_prop<<<NN, 288>>>(k);

    dim3 g(4 * (FOUT / BN), (NN + BM - 1) / BM);
    k_gemm<<<g, 128, SMEM_GEMM>>>(B0v, B1v, B2v, B3v, out);
}

// round 6
// speedup vs baseline: 3.8741x; 1.4875x over previous
#include <cuda_runtime.h>
#include <cuda_fp16.h>
#include <cstdint>

#define NN   10000
#define EE   160000
#define FIN  1152
#define FOUT 288
#define KMAX 7
#define LDT  (KMAX*FIN)   /* 8064 */
#define LDT4 (LDT/4)      /* 2016 */

// ---------------- device scratch ----------------------------------------------
__device__ float4 g_T4[(size_t)KMAX * NN * (FIN/4)];   // fp32 T (recurrence)
#define G_T ((float*)g_T4)
__device__ __half g_Th[(size_t)KMAX * NN * FIN];       // fp16 T (GEMM A), 161 MB

__device__ int   g_deg[NN];
__device__ float g_dinv[NN];
__device__ int   g_cnt[NN];
__device__ int   g_colptr[NN + 1];
__device__ int   g_cursor[NN];
__device__ int   g_src[EE];
__device__ float g_w[EE];

// fp16 W, transposed to K-major [n][k] per conv, packed
#define WH_OFF0 0
#define WH_OFF1 (4*FIN*FOUT)
#define WH_OFF2 (WH_OFF1 + 5*FIN*FOUT)
#define WH_OFF3 (WH_OFF2 + 6*FIN*FOUT)
#define WH_TOT  (WH_OFF3 + 7*FIN*FOUT)
__device__ __half g_Wh[WH_TOT];

// ---------------- helpers -------------------------------------------------------
__device__ __forceinline__ uint32_t smem_u32(const void* p) {
    return (uint32_t)__cvta_generic_to_shared(p);
}
__device__ __forceinline__ void cp16(uint32_t s, const void* g) {
    asm volatile("cp.async.cg.shared.global [%0], [%1], 16;"
                 :: "r"(s), "l"(__cvta_generic_to_global(g)) : "memory");
}
__device__ __forceinline__ void mma_f16(float* d, const uint32_t* a, const uint32_t* b) {
    asm volatile(
        "mma.sync.aligned.m16n8k16.row.col.f32.f16.f16.f32 "
        "{%0,%1,%2,%3}, {%4,%5,%6,%7}, {%8,%9}, {%0,%1,%2,%3};"
        : "+f"(d[0]), "+f"(d[1]), "+f"(d[2]), "+f"(d[3])
        : "r"(a[0]), "r"(a[1]), "r"(a[2]), "r"(a[3]), "r"(b[0]), "r"(b[1]));
}

// ---------------- setup kernels ------------------------------------------------
__global__ void k_zero() {
    int i = blockIdx.x * blockDim.x + threadIdx.x;
    if (i < NN) { g_deg[i] = 0; g_cnt[i] = 0; g_cursor[i] = 0; }
}
__global__ void k_hist(const int* __restrict__ ei) {
    int e = blockIdx.x * blockDim.x + threadIdx.x;
    if (e < EE) {
        atomicAdd(&g_deg[ei[e]], 1);
        atomicAdd(&g_cnt[ei[EE + e]], 1);
    }
}
__global__ void k_dinv() {
    int i = blockIdx.x * blockDim.x + threadIdx.x;
    if (i < NN) {
        int d = g_deg[i];
        g_dinv[i] = (d > 0) ? rsqrtf((float)d) : 0.0f;
    }
}
__global__ void k_scan() {
    __shared__ int wsum[32];
    const int tid  = threadIdx.x;
    const int lane = tid & 31;
    const int warp = tid >> 5;

    int v[10];
    int s = 0;
#pragma unroll
    for (int i = 0; i < 10; i++) {
        int idx = tid * 10 + i;
        v[i] = (idx < NN) ? g_cnt[idx] : 0;
        s += v[i];
    }
    int inc = s;
#pragma unroll
    for (int off = 1; off < 32; off <<= 1) {
        int n = __shfl_up_sync(0xFFFFFFFF, inc, off);
        if (lane >= off) inc += n;
    }
    if (lane == 31) wsum[warp] = inc;
    __syncthreads();
    if (warp == 0) {
        int w = wsum[lane];
#pragma unroll
        for (int off = 1; off < 32; off <<= 1) {
            int n = __shfl_up_sync(0xFFFFFFFF, w, off);
            if (lane >= off) w += n;
        }
        wsum[lane] = w;
    }
    __syncthreads();
    int base = (warp > 0 ? wsum[warp - 1] : 0) + inc - s;
#pragma unroll
    for (int i = 0; i < 10; i++) {
        int idx = tid * 10 + i;
        if (idx < NN) g_colptr[idx] = base;
        base += v[i];
    }
    if (tid == 1023) g_colptr[NN] = wsum[31];
}
__global__ void k_scatter(const int* __restrict__ ei) {
    int e = blockIdx.x * blockDim.x + threadIdx.x;
    if (e < EE) {
        int r = ei[e];
        int c = ei[EE + e];
        int p = g_colptr[c] + atomicAdd(&g_cursor[c], 1);
        g_src[p] = r;
        g_w[p]   = -(g_dinv[r] * g_dinv[c]);
    }
}
__global__ void k_copyx(const float* __restrict__ x) {
    const int total = NN * (FIN / 4);
    for (int idx = blockIdx.x * blockDim.x + threadIdx.x; idx < total;
         idx += gridDim.x * blockDim.x) {
        int node = idx / (FIN / 4);
        int r    = idx - node * (FIN / 4);
        float4 v = ((const float4*)x)[idx];
        g_T4[(size_t)node * LDT4 + r] = v;
        const size_t hp = (size_t)node * LDT + (size_t)r * 4;
        *(__half2*)(g_Th + hp)     = __floats2half2_rn(v.x, v.y);
        *(__half2*)(g_Th + hp + 2) = __floats2half2_rn(v.z, v.w);
    }
}
// W[k][n] fp32 (n contiguous) -> g_Wh[woff + n*KT + k] fp16
__global__ void k_wt(const float* __restrict__ W, int woff, int KT) {
    __shared__ float tile[32][33];
    const int tx = threadIdx.x, ty = threadIdx.y;
    const int n0 = blockIdx.x * 32;
    const int k0 = blockIdx.y * 32;
#pragma unroll
    for (int r = 0; r < 4; r++) {
        int a = ty + 8 * r;
        tile[a][tx] = W[(size_t)(k0 + a) * FOUT + n0 + tx];
    }
    __syncthreads();
#pragma unroll
    for (int r = 0; r < 4; r++) {
        int a = ty + 8 * r;
        g_Wh[(size_t)woff + (size_t)(n0 + a) * KT + k0 + tx] = __float2half_rn(tile[tx][a]);
    }
}

// ---------------- Chebyshev propagation ----------------------------------------
__global__ void k_prop(int kcur) {
    const int node = blockIdx.x;
    const int tid  = threadIdx.x;
    const int beg  = g_colptr[node];
    const int end  = g_colptr[node + 1];

    __shared__ int   ss[64];
    __shared__ float sw[64];

    float4 acc = make_float4(0.f, 0.f, 0.f, 0.f);
    const size_t foff  = (size_t)tid * 4;
    const size_t kprev = (size_t)(kcur - 1) * FIN;

    for (int b0 = beg; b0 < end; b0 += 64) {
        int cnt = min(64, end - b0);
        __syncthreads();
        if (tid < cnt) { ss[tid] = g_src[b0 + tid]; sw[tid] = g_w[b0 + tid]; }
        __syncthreads();
        for (int j = 0; j < cnt; j++) {
            float w = sw[j];
            const float4 v = *(const float4*)(G_T + (size_t)ss[j] * LDT + kprev + foff);
            acc.x += w * v.x; acc.y += w * v.y; acc.z += w * v.z; acc.w += w * v.w;
        }
    }

    const size_t nb = (size_t)node * LDT;
    float4 r;
    if (kcur == 1) {
        r = acc;
    } else {
        const float4 p = *(const float4*)(G_T + nb + (size_t)(kcur - 2) * FIN + foff);
        r.x = 2.f * acc.x - p.x; r.y = 2.f * acc.y - p.y;
        r.z = 2.f * acc.z - p.z; r.w = 2.f * acc.w - p.w;
    }
    const size_t pos = nb + (size_t)kcur * FIN + foff;
    if (kcur < KMAX - 1) *(float4*)(G_T + pos) = r;
    *(__half2*)(g_Th + pos)     = __floats2half2_rn(r.x, r.y);
    *(__half2*)(g_Th + pos + 2) = __floats2half2_rn(r.z, r.w);
}

// ---------------- fp16 mma.sync GEMM (4-stage cp.async) --------------------------
// 128 threads, 4 warps (2M x 2N), warp tile 64x72; m16n8k16; BK=32 halves.
#define BM 128
#define BN 144
#define BK 32
#define ASTRH 40               /* A row stride in halves (20 words) */
#define BSTRH 40               /* B row stride in halves */
#define STAGES 4
#define A_STH (BM*ASTRH)       /* halves per A stage: 5120 (10240 B) */
#define B_STH (BN*BSTRH)       /* halves per B stage: 5760 (11520 B) */
#define SMEM_GEMM ((STAGES*(A_STH+B_STH))*2)   /* 87040 B */

__global__ void __launch_bounds__(128, 2) k_gemm(
    const float* __restrict__ B0, const float* __restrict__ B1,
    const float* __restrict__ B2, const float* __restrict__ B3,
    float* __restrict__ out)
{
    extern __shared__ __align__(16) __half smp[];
    __half* Abase = smp;
    __half* Bbase = smp + STAGES * A_STH;

    const int c  = 3 - (blockIdx.x & 3);          // heavy convs first
    const int nb = blockIdx.x >> 2;
    const int Kc = 4 + c;
    const int KT = Kc * FIN;
    const int woff = (c == 0) ? WH_OFF0 : (c == 1) ? WH_OFF1 : (c == 2) ? WH_OFF2 : WH_OFF3;
    const __half* W  = g_Wh + woff;
    const float* Bv = (c == 0) ? B0 : (c == 1) ? B1 : (c == 2) ? B2 : B3;

    const int m0  = blockIdx.y * BM;
    const int n0  = nb * BN;
    const int t   = threadIdx.x;
    const int lane = t & 31;
    const int wid  = t >> 5;
    const int warpM = wid >> 1;
    const int warpN = wid & 1;
    const int lq = lane >> 2;
    const int lr = lane & 3;

    // ---- staging coordinates ----
    // A: 128 rows x 32 halves = 512 x 16B chunks; thread t -> row t>>2, chunk t&3
    const int ar0 = t >> 2, ach = (t & 3) * 8;    // half offset within row
    const __half* a_src[4];
    uint32_t a_dst[4];
#pragma unroll
    for (int i = 0; i < 4; i++) {
        int row = ar0 + 32 * i;
        int gm = m0 + row; gm = (gm < NN) ? gm : (NN - 1);
        a_src[i] = g_Th + (size_t)gm * LDT + ach;
        a_dst[i] = smem_u32(&Abase[row * ASTRH + ach]);
    }
    // B: 144 rows(n) x 32 halves = 576 chunks; j = t + 128*i (i<4), plus 512+t (t<64)
    int brow[5], bch[5];
#pragma unroll
    for (int i = 0; i < 5; i++) {
        int j = t + 128 * i;
        brow[i] = j >> 2;
        bch[i]  = (j & 3) * 8;
    }
    const bool b5 = (t < 64);
    uint32_t b_dst[5];
#pragma unroll
    for (int i = 0; i < 5; i++)
        b_dst[i] = smem_u32(&Bbase[brow[i] * BSTRH + bch[i]]);
    const __half* b_src[5];
#pragma unroll
    for (int i = 0; i < 5; i++)
        b_src[i] = W + (size_t)(n0 + brow[i]) * KT + bch[i];

    float d[4][9][4];
#pragma unroll
    for (int i = 0; i < 4; i++)
#pragma unroll
        for (int j = 0; j < 9; j++)
#pragma unroll
            for (int q = 0; q < 4; q++) d[i][j][q] = 0.f;

    const int ntiles = KT / BK;

    // prologue: stages 0..2
#pragma unroll
    for (int s = 0; s < STAGES - 1; s++) {
        const int k0 = s * BK;
        const uint32_t ao = s * (A_STH * 2);
        const uint32_t bo = s * (B_STH * 2);
#pragma unroll
        for (int i = 0; i < 4; i++) cp16(a_dst[i] + ao, a_src[i] + k0);
#pragma unroll
        for (int i = 0; i < 4; i++) cp16(b_dst[i] + bo, b_src[i] + k0);
        if (b5) cp16(b_dst[4] + bo, b_src[4] + k0);
        asm volatile("cp.async.commit_group;" ::: "memory");
    }

    for (int it = 0; it < ntiles; ++it) {
        asm volatile("cp.async.wait_group %0;" :: "n"(STAGES - 2) : "memory");
        __syncthreads();

        {
            const int ld = it + STAGES - 1;
            if (ld < ntiles) {
                const int s = ld & (STAGES - 1);
                const int k0 = ld * BK;
                const uint32_t ao = s * (A_STH * 2);
                const uint32_t bo = s * (B_STH * 2);
#pragma unroll
                for (int i = 0; i < 4; i++) cp16(a_dst[i] + ao, a_src[i] + k0);
#pragma unroll
                for (int i = 0; i < 4; i++) cp16(b_dst[i] + bo, b_src[i] + k0);
                if (b5) cp16(b_dst[4] + bo, b_src[4] + k0);
            }
            asm volatile("cp.async.commit_group;" ::: "memory");
        }

        const __half* As_ = Abase + (it & (STAGES - 1)) * A_STH;
        const __half* Bs_ = Bbase + (it & (STAGES - 1)) * B_STH;
#pragma unroll
        for (int ks = 0; ks < 2; ks++) {
            const int kb = ks * 16;     // half offset of this k16 step
            uint32_t a[4][4];
#pragma unroll
            for (int mt = 0; mt < 4; mt++) {
                const int mrow = warpM * 64 + mt * 16 + lq;
                const __half* p0 = As_ + mrow * ASTRH + kb + lr * 2;
                const __half* p1 = As_ + (mrow + 8) * ASTRH + kb + lr * 2;
                a[mt][0] = *(const uint32_t*)(p0);
                a[mt][1] = *(const uint32_t*)(p1);
                a[mt][2] = *(const uint32_t*)(p0 + 8);
                a[mt][3] = *(const uint32_t*)(p1 + 8);
            }
            uint32_t b[9][2];
#pragma unroll
            for (int nt = 0; nt < 9; nt++) {
                const int ncol = warpN * 72 + nt * 8 + lq;
                const __half* p = Bs_ + ncol * BSTRH + kb + lr * 2;
                b[nt][0] = *(const uint32_t*)(p);
                b[nt][1] = *(const uint32_t*)(p + 8);
            }
#pragma unroll
            for (int mt = 0; mt < 4; mt++)
#pragma unroll
                for (int nt = 0; nt < 9; nt++)
                    mma_f16(d[mt][nt], a[mt], b[nt]);
        }
    }

    // epilogue: bias + store
#pragma unroll
    for (int mt = 0; mt < 4; mt++) {
        const int row0 = m0 + warpM * 64 + mt * 16 + lq;
        const int row1 = row0 + 8;
#pragma unroll
        for (int nt = 0; nt < 9; nt++) {
            const int col = warpN * 72 + nt * 8 + lr * 2;
            const float bx = __ldg(&Bv[n0 + col]);
            const float by = __ldg(&Bv[n0 + col + 1]);
            const size_t oc = (size_t)c * FOUT + n0 + col;
            if (row0 < NN) {
                float2 v = make_float2(d[mt][nt][0] + bx, d[mt][nt][1] + by);
                *(float2*)&out[(size_t)row0 * 1152 + oc] = v;
            }
            if (row1 < NN) {
                float2 v = make_float2(d[mt][nt][2] + bx, d[mt][nt][3] + by);
                *(float2*)&out[(size_t)row1 * 1152 + oc] = v;
            }
        }
    }
}

// ---------------- launch --------------------------------------------------------
extern "C" void kernel_launch(void* const* d_in, const int* in_sizes, int n_in,
                              void* d_out, int out_size) {
    const float* x   = (const float*)d_in[0];
    const int*   ei  = (const int*)d_in[1];
    const float* W0  = (const float*)d_in[2];
    const float* B0v = (const float*)d_in[3];
    const float* W1  = (const float*)d_in[4];
    const float* B1v = (const float*)d_in[5];
    const float* W2  = (const float*)d_in[6];
    const float* B2v = (const float*)d_in[7];
    const float* W3  = (const float*)d_in[8];
    const float* B3v = (const float*)d_in[9];
    float* out = (float*)d_out;

    cudaFuncSetAttribute(k_gemm, cudaFuncAttributeMaxDynamicSharedMemorySize, SMEM_GEMM);

    k_zero<<<(NN + 255) / 256, 256>>>();
    k_hist<<<(EE + 255) / 256, 256>>>(ei);
    k_dinv<<<(NN + 255) / 256, 256>>>();
    k_scan<<<1, 1024>>>();
    k_scatter<<<(EE + 255) / 256, 256>>>(ei);
    k_copyx<<<4096, 256>>>(x);

    dim3 tb(32, 8);
    k_wt<<<dim3(9, 4 * 36), tb>>>(W0, WH_OFF0, 4 * FIN);
    k_wt<<<dim3(9, 5 * 36), tb>>>(W1, WH_OFF1, 5 * FIN);
    k_wt<<<dim3(9, 6 * 36), tb>>>(W2, WH_OFF2, 6 * FIN);
    k_wt<<<dim3(9, 7 * 36), tb>>>(W3, WH_OFF3, 7 * FIN);

    for (int k = 1; k < KMAX; k++)
        k_prop<<<NN, 288>>>(k);

    dim3 g(4 * (FOUT / BN), (NN + BM - 1) / BM);
    k_gemm<<<g, 128, SMEM_GEMM>>>(B0v, B1v, B2v, B3v, out);
}

// round 7
// speedup vs baseline: 4.4274x; 1.1428x over previous
#include <cuda_runtime.h>
#include <cuda_fp16.h>
#include <cstdint>

#define NN   10000
#define EE   160000
#define FIN  1152
#define FOUT 288
#define KMAX 7
#define LDT  (KMAX*FIN)   /* 8064 */
#define LDT4 (LDT/4)      /* 2016 */

// ---------------- device scratch ----------------------------------------------
__device__ float4 g_T4[(size_t)KMAX * NN * (FIN/4)];   // fp32 T (recurrence)
#define G_T ((float*)g_T4)
__device__ __half g_Th[(size_t)KMAX * NN * FIN];       // fp16 T (GEMM A)

__device__ int   g_deg[NN];
__device__ float g_dinv[NN];
__device__ int   g_cnt[NN];
__device__ int   g_colptr[NN + 1];
__device__ int   g_cursor[NN];
__device__ int   g_src[EE];
__device__ float g_w[EE];

// fp16 W, transposed to K-major [n][k] per conv, packed
#define WH_OFF0 0
#define WH_OFF1 (4*FIN*FOUT)
#define WH_OFF2 (WH_OFF1 + 5*FIN*FOUT)
#define WH_OFF3 (WH_OFF2 + 6*FIN*FOUT)
#define WH_TOT  (WH_OFF3 + 7*FIN*FOUT)
__device__ __half g_Wh[WH_TOT];

// ---------------- helpers -------------------------------------------------------
__device__ __forceinline__ uint32_t smem_u32(const void* p) {
    return (uint32_t)__cvta_generic_to_shared(p);
}
__device__ __forceinline__ void cp16(uint32_t s, const void* g) {
    asm volatile("cp.async.cg.shared.global [%0], [%1], 16;"
                 :: "r"(s), "l"(__cvta_generic_to_global(g)) : "memory");
}
__device__ __forceinline__ void mma_f16(float* d, const uint32_t* a, const uint32_t* b) {
    asm volatile(
        "mma.sync.aligned.m16n8k16.row.col.f32.f16.f16.f32 "
        "{%0,%1,%2,%3}, {%4,%5,%6,%7}, {%8,%9}, {%0,%1,%2,%3};"
        : "+f"(d[0]), "+f"(d[1]), "+f"(d[2]), "+f"(d[3])
        : "r"(a[0]), "r"(a[1]), "r"(a[2]), "r"(a[3]), "r"(b[0]), "r"(b[1]));
}
__device__ __forceinline__ void ldsm4(uint32_t* r, uint32_t addr) {
    asm volatile("ldmatrix.sync.aligned.m8n8.x4.shared.b16 {%0,%1,%2,%3}, [%4];"
                 : "=r"(r[0]), "=r"(r[1]), "=r"(r[2]), "=r"(r[3]) : "r"(addr));
}
__device__ __forceinline__ void ldsm2(uint32_t* r, uint32_t addr) {
    asm volatile("ldmatrix.sync.aligned.m8n8.x2.shared.b16 {%0,%1}, [%2];"
                 : "=r"(r[0]), "=r"(r[1]) : "r"(addr));
}

// ---------------- setup kernels ------------------------------------------------
__global__ void k_zero() {
    int i = blockIdx.x * blockDim.x + threadIdx.x;
    if (i < NN) { g_deg[i] = 0; g_cnt[i] = 0; g_cursor[i] = 0; }
}
__global__ void k_hist(const int* __restrict__ ei) {
    int e = blockIdx.x * blockDim.x + threadIdx.x;
    if (e < EE) {
        atomicAdd(&g_deg[ei[e]], 1);
        atomicAdd(&g_cnt[ei[EE + e]], 1);
    }
}
// scan of g_cnt -> g_colptr, fused with dinv computation
__global__ void k_scan() {
    __shared__ int wsum[32];
    const int tid  = threadIdx.x;
    const int lane = tid & 31;
    const int warp = tid >> 5;

    int v[10];
    int s = 0;
#pragma unroll
    for (int i = 0; i < 10; i++) {
        int idx = tid * 10 + i;
        if (idx < NN) {
            v[i] = g_cnt[idx];
            int dg = g_deg[idx];
            g_dinv[idx] = (dg > 0) ? rsqrtf((float)dg) : 0.0f;
        } else v[i] = 0;
        s += v[i];
    }
    int inc = s;
#pragma unroll
    for (int off = 1; off < 32; off <<= 1) {
        int n = __shfl_up_sync(0xFFFFFFFF, inc, off);
        if (lane >= off) inc += n;
    }
    if (lane == 31) wsum[warp] = inc;
    __syncthreads();
    if (warp == 0) {
        int w = wsum[lane];
#pragma unroll
        for (int off = 1; off < 32; off <<= 1) {
            int n = __shfl_up_sync(0xFFFFFFFF, w, off);
            if (lane >= off) w += n;
        }
        wsum[lane] = w;
    }
    __syncthreads();
    int base = (warp > 0 ? wsum[warp - 1] : 0) + inc - s;
#pragma unroll
    for (int i = 0; i < 10; i++) {
        int idx = tid * 10 + i;
        if (idx < NN) g_colptr[idx] = base;
        base += v[i];
    }
    if (tid == 1023) g_colptr[NN] = wsum[31];
}
__global__ void k_scatter(const int* __restrict__ ei) {
    int e = blockIdx.x * blockDim.x + threadIdx.x;
    if (e < EE) {
        int r = ei[e];
        int c = ei[EE + e];
        int p = g_colptr[c] + atomicAdd(&g_cursor[c], 1);
        g_src[p] = r;
        g_w[p]   = -(g_dinv[r] * g_dinv[c]);
    }
}
__global__ void k_copyx(const float* __restrict__ x) {
    const int total = NN * (FIN / 4);
    for (int idx = blockIdx.x * blockDim.x + threadIdx.x; idx < total;
         idx += gridDim.x * blockDim.x) {
        int node = idx / (FIN / 4);
        int r    = idx - node * (FIN / 4);
        float4 v = ((const float4*)x)[idx];
        g_T4[(size_t)node * LDT4 + r] = v;
        const size_t hp = (size_t)node * LDT + (size_t)r * 4;
        *(__half2*)(g_Th + hp)     = __floats2half2_rn(v.x, v.y);
        *(__half2*)(g_Th + hp + 2) = __floats2half2_rn(v.z, v.w);
    }
}
// all 4 convs: W[k][n] fp32 -> g_Wh[woff + n*KT + k] fp16
__global__ void k_wt(const float* __restrict__ W0, const float* __restrict__ W1,
                     const float* __restrict__ W2, const float* __restrict__ W3) {
    __shared__ float tile[32][33];
    const int c  = blockIdx.z;
    const int KT = (4 + c) * FIN;
    const int k0 = blockIdx.y * 32;
    if (k0 >= KT) return;
    const float* W = (c == 0) ? W0 : (c == 1) ? W1 : (c == 2) ? W2 : W3;
    const int woff = (c == 0) ? WH_OFF0 : (c == 1) ? WH_OFF1 : (c == 2) ? WH_OFF2 : WH_OFF3;
    const int tx = threadIdx.x, ty = threadIdx.y;
    const int n0 = blockIdx.x * 32;
#pragma unroll
    for (int r = 0; r < 4; r++) {
        int a = ty + 8 * r;
        tile[a][tx] = W[(size_t)(k0 + a) * FOUT + n0 + tx];
    }
    __syncthreads();
#pragma unroll
    for (int r = 0; r < 4; r++) {
        int a = ty + 8 * r;
        g_Wh[(size_t)woff + (size_t)(n0 + a) * KT + k0 + tx] = __float2half_rn(tile[tx][a]);
    }
}

// ---------------- Chebyshev propagation ----------------------------------------
__global__ void k_prop(int kcur) {
    const int node = blockIdx.x;
    const int tid  = threadIdx.x;
    const int beg  = g_colptr[node];
    const int end  = g_colptr[node + 1];

    __shared__ int   ss[64];
    __shared__ float sw[64];

    float4 acc = make_float4(0.f, 0.f, 0.f, 0.f);
    const size_t foff  = (size_t)tid * 4;
    const size_t kprev = (size_t)(kcur - 1) * FIN;

    for (int b0 = beg; b0 < end; b0 += 64) {
        int cnt = min(64, end - b0);
        __syncthreads();
        if (tid < cnt) { ss[tid] = g_src[b0 + tid]; sw[tid] = g_w[b0 + tid]; }
        __syncthreads();
        for (int j = 0; j < cnt; j++) {
            float w = sw[j];
            const float4 v = *(const float4*)(G_T + (size_t)ss[j] * LDT + kprev + foff);
            acc.x += w * v.x; acc.y += w * v.y; acc.z += w * v.z; acc.w += w * v.w;
        }
    }

    const size_t nb = (size_t)node * LDT;
    float4 r;
    if (kcur == 1) {
        r = acc;
    } else {
        const float4 p = *(const float4*)(G_T + nb + (size_t)(kcur - 2) * FIN + foff);
        r.x = 2.f * acc.x - p.x; r.y = 2.f * acc.y - p.y;
        r.z = 2.f * acc.z - p.z; r.w = 2.f * acc.w - p.w;
    }
    const size_t pos = nb + (size_t)kcur * FIN + foff;
    if (kcur < KMAX - 1) *(float4*)(G_T + pos) = r;
    *(__half2*)(g_Th + pos)     = __floats2half2_rn(r.x, r.y);
    *(__half2*)(g_Th + pos + 2) = __floats2half2_rn(r.z, r.w);
}

// ---------------- fp16 mma.sync GEMM (ldmatrix + 4-stage cp.async) ---------------
#define BM 128
#define BN 144
#define BK 32
#define ASTRH 40
#define BSTRH 40
#define STAGES 4
#define A_STH (BM*ASTRH)       /* 5120 halves */
#define B_STH (BN*BSTRH)       /* 5760 halves */
#define SMEM_GEMM ((STAGES*(A_STH+B_STH))*2)   /* 87040 B */

__global__ void __launch_bounds__(128, 2) k_gemm(
    const float* __restrict__ B0, const float* __restrict__ B1,
    const float* __restrict__ B2, const float* __restrict__ B3,
    float* __restrict__ out)
{
    extern __shared__ __align__(16) __half smp[];
    __half* Abase = smp;
    __half* Bbase = smp + STAGES * A_STH;
    const uint32_t sAu = smem_u32(Abase);
    const uint32_t sBu = smem_u32(Bbase);

    const int c  = 3 - (blockIdx.x & 3);          // heavy convs first
    const int nb = blockIdx.x >> 2;
    const int Kc = 4 + c;
    const int KT = Kc * FIN;
    const int woff = (c == 0) ? WH_OFF0 : (c == 1) ? WH_OFF1 : (c == 2) ? WH_OFF2 : WH_OFF3;
    const __half* W  = g_Wh + woff;
    const float* Bv = (c == 0) ? B0 : (c == 1) ? B1 : (c == 2) ? B2 : B3;

    const int m0  = blockIdx.y * BM;
    const int n0  = nb * BN;
    const int t   = threadIdx.x;
    const int lane = t & 31;
    const int wid  = t >> 5;
    const int warpM = wid >> 1;
    const int warpN = wid & 1;
    const int lq = lane >> 2;
    const int lr = lane & 3;

    // ---- ldmatrix lane offsets (halves, within a stage) ----
    // A x4: lanes 0-7: m(0-7) k0 | 8-15: m+8 k0 | 16-23: m(0-7) k8 | 24-31: m+8 k8
    const int a_lm = (warpM * 64 + (lane & 7) + (lane & 8)) * ASTRH + ((lane & 16) >> 1);
    // B x4 (pairs): 0-7: n(0-7) k0 | 8-15: n(0-7) k8 | 16-23: n+8 k0 | 24-31: n+8 k8
    const int b_lm = (warpN * 72 + (lane & 7) + ((lane & 16) >> 1)) * BSTRH + (lane & 8);
    // B x2 (last nt=8): 0-7: n(64-71) k0 | 8-15: same n, k8
    const int bs_lm = (warpN * 72 + 64 + (lane & 7)) * BSTRH + (lane & 8);

    // ---- staging coordinates ----
    const int ar0 = t >> 2, ach = (t & 3) * 8;
    const __half* a_src[4];
    uint32_t a_dst[4];
#pragma unroll
    for (int i = 0; i < 4; i++) {
        int row = ar0 + 32 * i;
        int gm = m0 + row; gm = (gm < NN) ? gm : (NN - 1);
        a_src[i] = g_Th + (size_t)gm * LDT + ach;
        a_dst[i] = sAu + (row * ASTRH + ach) * 2;
    }
    int brow[5], bch[5];
#pragma unroll
    for (int i = 0; i < 5; i++) {
        int j = t + 128 * i;
        brow[i] = j >> 2;
        bch[i]  = (j & 3) * 8;
    }
    const bool b5 = (t < 64);
    uint32_t b_dst[5];
    const __half* b_src[5];
#pragma unroll
    for (int i = 0; i < 5; i++) {
        b_dst[i] = sBu + (brow[i] * BSTRH + bch[i]) * 2;
        b_src[i] = W + (size_t)(n0 + brow[i]) * KT + bch[i];
    }

    float d[4][9][4];
#pragma unroll
    for (int i = 0; i < 4; i++)
#pragma unroll
        for (int j = 0; j < 9; j++)
#pragma unroll
            for (int q = 0; q < 4; q++) d[i][j][q] = 0.f;

    const int ntiles = KT / BK;

    // prologue: stages 0..2
#pragma unroll
    for (int s = 0; s < STAGES - 1; s++) {
        const int k0 = s * BK;
        const uint32_t ao = s * (A_STH * 2);
        const uint32_t bo = s * (B_STH * 2);
#pragma unroll
        for (int i = 0; i < 4; i++) cp16(a_dst[i] + ao, a_src[i] + k0);
#pragma unroll
        for (int i = 0; i < 4; i++) cp16(b_dst[i] + bo, b_src[i] + k0);
        if (b5) cp16(b_dst[4] + bo, b_src[4] + k0);
        asm volatile("cp.async.commit_group;" ::: "memory");
    }

    for (int it = 0; it < ntiles; ++it) {
        asm volatile("cp.async.wait_group %0;" :: "n"(STAGES - 2) : "memory");
        __syncthreads();

        {
            const int ld = it + STAGES - 1;
            if (ld < ntiles) {
                const int s = ld & (STAGES - 1);
                const int k0 = ld * BK;
                const uint32_t ao = s * (A_STH * 2);
                const uint32_t bo = s * (B_STH * 2);
#pragma unroll
                for (int i = 0; i < 4; i++) cp16(a_dst[i] + ao, a_src[i] + k0);
#pragma unroll
                for (int i = 0; i < 4; i++) cp16(b_dst[i] + bo, b_src[i] + k0);
                if (b5) cp16(b_dst[4] + bo, b_src[4] + k0);
            }
            asm volatile("cp.async.commit_group;" ::: "memory");
        }

        const int st = it & (STAGES - 1);
        const uint32_t sA = sAu + st * (A_STH * 2);
        const uint32_t sB = sBu + st * (B_STH * 2);
#pragma unroll
        for (int ks = 0; ks < 2; ks++) {
            const int kb = ks * 16;
            uint32_t a[4][4], b[9][2];
#pragma unroll
            for (int mt = 0; mt < 4; mt++)
                ldsm4(a[mt], sA + (a_lm + mt * 16 * ASTRH + kb) * 2);
#pragma unroll
            for (int np = 0; np < 4; np++) {
                uint32_t r4[4];
                ldsm4(r4, sB + (b_lm + np * 16 * BSTRH + kb) * 2);
                b[2 * np][0] = r4[0]; b[2 * np][1] = r4[1];
                b[2 * np + 1][0] = r4[2]; b[2 * np + 1][1] = r4[3];
            }
            ldsm2(b[8], sB + (bs_lm + kb) * 2);
#pragma unroll
            for (int mt = 0; mt < 4; mt++)
#pragma unroll
                for (int nt = 0; nt < 9; nt++)
                    mma_f16(d[mt][nt], a[mt], b[nt]);
        }
    }

    // epilogue: bias + store
#pragma unroll
    for (int mt = 0; mt < 4; mt++) {
        const int row0 = m0 + warpM * 64 + mt * 16 + lq;
        const int row1 = row0 + 8;
#pragma unroll
        for (int nt = 0; nt < 9; nt++) {
            const int col = warpN * 72 + nt * 8 + lr * 2;
            const float bx = __ldg(&Bv[n0 + col]);
            const float by = __ldg(&Bv[n0 + col + 1]);
            const size_t oc = (size_t)c * FOUT + n0 + col;
            if (row0 < NN) {
                float2 v = make_float2(d[mt][nt][0] + bx, d[mt][nt][1] + by);
                *(float2*)&out[(size_t)row0 * 1152 + oc] = v;
            }
            if (row1 < NN) {
                float2 v = make_float2(d[mt][nt][2] + bx, d[mt][nt][3] + by);
                *(float2*)&out[(size_t)row1 * 1152 + oc] = v;
            }
        }
    }
}

// ---------------- launch --------------------------------------------------------
extern "C" void kernel_launch(void* const* d_in, const int* in_sizes, int n_in,
                              void* d_out, int out_size) {
    const float* x   = (const float*)d_in[0];
    const int*   ei  = (const int*)d_in[1];
    const float* W0  = (const float*)d_in[2];
    const float* B0v = (const float*)d_in[3];
    const float* W1  = (const float*)d_in[4];
    const float* B1v = (const float*)d_in[5];
    const float* W2  = (const float*)d_in[6];
    const float* B2v = (const float*)d_in[7];
    const float* W3  = (const float*)d_in[8];
    const float* B3v = (const float*)d_in[9];
    float* out = (float*)d_out;

    cudaFuncSetAttribute(k_gemm, cudaFuncAttributeMaxDynamicSharedMemorySize, SMEM_GEMM);

    k_zero<<<(NN + 255) / 256, 256>>>();
    k_hist<<<(EE + 255) / 256, 256>>>(ei);
    k_scan<<<1, 1024>>>();
    k_scatter<<<(EE + 255) / 256, 256>>>(ei);
    k_copyx<<<4096, 256>>>(x);

    dim3 tb(32, 8);
    k_wt<<<dim3(9, 7 * 36, 4), tb>>>(W0, W1, W2, W3);

    for (int k = 1; k < KMAX; k++)
        k_prop<<<NN, 288>>>(k);

    dim3 g(4 * (FOUT / BN), (NN + BM - 1) / BM);
    k_gemm<<<g, 128, SMEM_GEMM>>>(B0v, B1v, B2v, B3v, out);
}